// round 10
// baseline (speedup 1.0000x reference)
#include <cuda_runtime.h>
#include <cuda_fp16.h>
#include <stdint.h>
#include <math.h>

#define T_TOKENS 4096
#define D_MODEL  1024
#define N_EXP    8
#define F_DIM    2048
#define LN_EPS   1e-5f
#define MAXP     4096

// tiles
#define BM 128
#define BN 128
#define BK 32
#define STAGES 3
// A buffer: 128 rows (m) x 64B (k-contiguous), stride 80 -> conflict-free
#define AROWB 80
#define ABUF  (128 * AROWB)             // 10240
// B buffer: 32 rows (k) x 256B (n-contiguous), stride 272 (68w === 4 mod 32)
#define BROWB 272
#define BBUF  (BK * BROWB)              // 8704
#define A_OFF 0
#define B_OFF ABUF
#define STG_BYTES (ABUF + BBUF)         // 18944 per stage
#define SMEM_BYTES (STAGES * STG_BYTES) // 56832 dynamic -> 2 CTAs/SM

__device__ __forceinline__ void mma16816(float* c, const uint32_t* a, const uint32_t* b) {
    asm volatile(
        "mma.sync.aligned.m16n8k16.row.col.f32.f16.f16.f32 "
        "{%0,%1,%2,%3}, {%4,%5,%6,%7}, {%8,%9}, {%0,%1,%2,%3};"
        : "+f"(c[0]), "+f"(c[1]), "+f"(c[2]), "+f"(c[3])
        : "r"(a[0]), "r"(a[1]), "r"(a[2]), "r"(a[3]), "r"(b[0]), "r"(b[1]));
}
__device__ __forceinline__ uint32_t smem_u32(const void* p) {
    uint32_t a;
    asm("{ .reg .u64 t; cvta.to.shared.u64 t, %1; cvt.u32.u64 %0, t; }"
        : "=r"(a) : "l"(p));
    return a;
}
__device__ __forceinline__ void cp16(uint32_t saddr, const void* g) {
    asm volatile("cp.async.cg.shared.global [%0], [%1], 16;"
                 :: "r"(saddr), "l"(g) : "memory");
}
#define CP_COMMIT() asm volatile("cp.async.commit_group;" ::: "memory")
#define CP_WAIT1()  asm volatile("cp.async.wait_group 1;" ::: "memory")

__device__ __forceinline__ void ldsm4(uint32_t* r, uint32_t addr) {
    asm volatile("ldmatrix.sync.aligned.m8n8.x4.shared.b16 {%0,%1,%2,%3}, [%4];"
                 : "=r"(r[0]), "=r"(r[1]), "=r"(r[2]), "=r"(r[3]) : "r"(addr));
}
__device__ __forceinline__ void ldsm4t(uint32_t* r, uint32_t addr) {
    asm volatile("ldmatrix.sync.aligned.m8n8.x4.trans.shared.b16 {%0,%1,%2,%3}, [%4];"
                 : "=r"(r[0]), "=r"(r[1]), "=r"(r[2]), "=r"(r[3]) : "r"(addr));
}

// ---------------- scratch ----------------
__device__ int   g_counts[N_EXP];
__device__ int   g_tok[N_EXP * MAXP];
__device__ float g_wt[N_EXP * MAXP];
__device__ int   g_slot[T_TOKENS * 2];
__device__ __align__(16) __half g_x16[(size_t)T_TOKENS * D_MODEL];
__device__ __align__(16) __half g_W1c[(size_t)N_EXP * D_MODEL * F_DIM]; // native [e][d][f]
__device__ __align__(16) __half g_W2c[(size_t)N_EXP * F_DIM * D_MODEL]; // native [e][f][d]
__device__ __align__(16) __half g_H16[(size_t)N_EXP * MAXP * F_DIM];
__device__ __align__(16) float  g_O[(size_t)N_EXP * MAXP * D_MODEL];

// ---------------------------------------------------------------------------
__global__ void init_kernel() {
    if (threadIdx.x < N_EXP) g_counts[threadIdx.x] = 0;
}

// ---------------------------------------------------------------------------
// Gating + fused fp32->fp16 conversion of x.
__global__ void gating_kernel(const float* __restrict__ x,
                              const float* __restrict__ Wg,
                              const float* __restrict__ bg) {
    int warp = threadIdx.x >> 5;
    int lane = threadIdx.x & 31;
    int t = blockIdx.x * 8 + warp;
    if (t >= T_TOKENS) return;

    float acc[8];
#pragma unroll
    for (int e = 0; e < 8; e++) acc[e] = 0.f;
    const float* xr = x + (size_t)t * D_MODEL;
    __half* xo = g_x16 + (size_t)t * D_MODEL;
    for (int k = lane; k < D_MODEL; k += 32) {
        float xv = xr[k];
        xo[k] = __float2half_rn(xv);
        float4 w0 = *(const float4*)(Wg + (size_t)k * 8);
        float4 w1 = *(const float4*)(Wg + (size_t)k * 8 + 4);
        acc[0] += xv * w0.x; acc[1] += xv * w0.y;
        acc[2] += xv * w0.z; acc[3] += xv * w0.w;
        acc[4] += xv * w1.x; acc[5] += xv * w1.y;
        acc[6] += xv * w1.z; acc[7] += xv * w1.w;
    }
#pragma unroll
    for (int e = 0; e < 8; e++)
#pragma unroll
        for (int off = 16; off > 0; off >>= 1)
            acc[e] += __shfl_down_sync(0xffffffffu, acc[e], off);

    if (lane == 0) {
        float v[8];
#pragma unroll
        for (int e = 0; e < 8; e++) v[e] = acc[e] + bg[e];
        int b0 = 0; float m0 = v[0];
#pragma unroll
        for (int e = 1; e < 8; e++) if (v[e] > m0) { m0 = v[e]; b0 = e; }
        int b1i = (b0 == 0) ? 1 : 0; float m1 = v[b1i];
#pragma unroll
        for (int e = 0; e < 8; e++)
            if (e != b0 && v[e] > m1) { m1 = v[e]; b1i = e; }

        float ex = expf(m1 - m0);
        float s  = 1.0f + ex;
        int p0 = atomicAdd(&g_counts[b0], 1);
        g_tok[b0 * MAXP + p0] = t;
        g_wt [b0 * MAXP + p0] = 1.0f / s;
        g_slot[t * 2 + 0] = b0 * MAXP + p0;
        int p1 = atomicAdd(&g_counts[b1i], 1);
        g_tok[b1i * MAXP + p1] = t;
        g_wt [b1i * MAXP + p1] = ex / s;
        g_slot[t * 2 + 1] = b1i * MAXP + p1;
    }
}

// ---------------------------------------------------------------------------
// Pure coalesced fp32->fp16 converts (no transpose needed anymore).
// Outputs are device-resolved symbols (GB300 ATS trap — see R3-R5 post-mortem).
__global__ void conv_w1_kernel(const float* __restrict__ W) {
    size_t i = (size_t)blockIdx.x * blockDim.x + threadIdx.x;  // group of 4
    float4 v = ((const float4*)W)[i];
    ((__half2*)g_W1c)[i * 2 + 0] = __floats2half2_rn(v.x, v.y);
    ((__half2*)g_W1c)[i * 2 + 1] = __floats2half2_rn(v.z, v.w);
}
__global__ void conv_w2_kernel(const float* __restrict__ W) {
    size_t i = (size_t)blockIdx.x * blockDim.x + threadIdx.x;
    float4 v = ((const float4*)W)[i];
    ((__half2*)g_W2c)[i * 2 + 0] = __floats2half2_rn(v.x, v.y);
    ((__half2*)g_W2c)[i * 2 + 1] = __floats2half2_rn(v.z, v.w);
}

// ---------------------------------------------------------------------------
// HMMA mainloop, cp.async 3-stage pipelined, fp16 single-pass.
// A staged [m][k] (k-contiguous, AROWB); B staged [k][n] (n-contiguous, BROWB)
// directly from the NATIVE weight layout; B fragments via ldmatrix.x4.trans.
struct Ptrs {
    const uint4* a;      // per-thread A row (at k=0)
    const uint4* b;      // per-thread B source (at k=0)
    int bstride;         // uint4 stride per k-tile for B source
};

__device__ __forceinline__ void cp_stage(uint32_t smbase, const Ptrs& rp,
                                         int s, int kt, int tid) {
    // A: thread t -> m-row t>>1, 32B half (t&1)
    int arow = tid >> 1, ahalf = tid & 1;
    uint32_t ad = smbase + s * STG_BYTES + A_OFF
                + (uint32_t)arow * AROWB + (uint32_t)ahalf * 32u;
    int aidx = kt * 4 + ahalf * 2;
    cp16(ad,      rp.a + aidx);
    cp16(ad + 16, rp.a + aidx + 1);
    // B: thread t -> k-row t>>3, 32B segment (t&7)
    int krow = tid >> 3, seg = tid & 7;
    uint32_t bd = smbase + s * STG_BYTES + B_OFF
                + (uint32_t)krow * BROWB + (uint32_t)seg * 32u;
    const uint4* bs = rp.b + (size_t)kt * rp.bstride;
    cp16(bd,      bs);
    cp16(bd + 16, bs + 1);
}

// A fragments: non-trans ldmatrix (verified R9).
// B fragments: ldmatrix.x4.trans on [k][n] storage. Lane group g = lane>>3:
//   g0=(k-oct0,n-oct0) g1=(k-oct1,n-oct0) g2=(k-oct0,n-oct1) g3=(k-oct1,n-oct1)
// -> regs (r0,r1)/(r2,r3) = (b0,b1) for n-octet 0/1, matching R9 convention.
__device__ __forceinline__ void compute_tiles(uint32_t sbase,
                                              const uint32_t aoff[4],
                                              const uint32_t boff[2],
                                              float c[4][4][4]) {
#pragma unroll
    for (int kk = 0; kk < 2; kk++) {
        uint32_t koA = (uint32_t)kk * 32u;           // 16 halves along k-contig A
        uint32_t koB = (uint32_t)kk * 16u * BROWB;   // 16 k-rows of B
        uint32_t a[4][4], b[2][4];
#pragma unroll
        for (int mt = 0; mt < 4; mt++)
            ldsm4(a[mt], sbase + A_OFF + aoff[mt] + koA);
#pragma unroll
        for (int p = 0; p < 2; p++)
            ldsm4t(b[p], sbase + B_OFF + boff[p] + koB);
#pragma unroll
        for (int mt = 0; mt < 4; mt++)
#pragma unroll
            for (int nt = 0; nt < 4; nt++)
                mma16816(c[mt][nt], a[mt], &b[nt >> 1][(nt & 1) * 2]);
    }
}

__device__ __forceinline__ void run_mainloop(uint32_t smbase,
                                             const Ptrs& rp, int ktiles,
                                             const uint32_t aoff[4],
                                             const uint32_t boff[2],
                                             float c[4][4][4], int tid) {
#pragma unroll
    for (int s = 0; s < STAGES - 1; s++) {
        cp_stage(smbase, rp, s, s, tid);
        CP_COMMIT();
    }
    for (int kt = 0; kt < ktiles; kt++) {
        CP_WAIT1();
        __syncthreads();
        int kn = kt + STAGES - 1;
        if (kn < ktiles) cp_stage(smbase, rp, kn % STAGES, kn, tid);
        CP_COMMIT();
        compute_tiles(smbase + (kt % STAGES) * STG_BYTES, aoff, boff, c);
    }
}

// lane offsets relative to operand buffer bases
__device__ __forceinline__ void make_offsets(int wr, int wc, int lane,
                                             uint32_t aoff[4], uint32_t boff[2]) {
#pragma unroll
    for (int mt = 0; mt < 4; mt++)
        aoff[mt] = (uint32_t)(wr * 64 + mt * 16 + (lane & 15)) * AROWB
                 + (uint32_t)(lane >> 4) * 16u;
    int g = lane >> 3, w = lane & 7;
#pragma unroll
    for (int p = 0; p < 2; p++) {
        int krow = (g & 1) * 8 + w;
        int ncol = wc * 32 + p * 16 + (g >> 1) * 8;
        boff[p] = (uint32_t)krow * BROWB + (uint32_t)ncol * 2u;
    }
}

// ---------------------------------------------------------------------------
// GEMM1: H[e-rows, F] = relu( Xg @ W1[e] + b1[e] )
__global__ void __launch_bounds__(256, 2)
gemm1_mma(const float* __restrict__ b1) {
    extern __shared__ __align__(16) char tiles[];
    uint32_t smbase = smem_u32(tiles);
    int e   = blockIdx.z;
    int cnt = g_counts[e];
    int m0  = blockIdx.y * BM;
    if (m0 >= cnt) return;
    int n0  = blockIdx.x * BN;
    int tid = threadIdx.x, lane = tid & 31, wid = tid >> 5;
    int wr = wid >> 2, wc = wid & 3;

    int arow = m0 + (tid >> 1); if (arow >= cnt) arow = cnt - 1;
    int tok  = g_tok[e * MAXP + arow];
    Ptrs rp;
    rp.a = (const uint4*)(g_x16 + (size_t)tok * D_MODEL);
    // B source: native [d][f]; thread covers k-row tid>>3, 16-half segment tid&7
    rp.b = (const uint4*)(g_W1c + ((size_t)e * D_MODEL + (tid >> 3)) * F_DIM
                          + n0 + (tid & 7) * 16);
    rp.bstride = BK * F_DIM / 8;   // uint4s per k-tile step

    uint32_t aoff[4], boff[2];
    make_offsets(wr, wc, lane, aoff, boff);

    float c[4][4][4];
#pragma unroll
    for (int i = 0; i < 4; i++)
#pragma unroll
        for (int j = 0; j < 4; j++)
#pragma unroll
            for (int k = 0; k < 4; k++) c[i][j][k] = 0.f;

    run_mainloop(smbase, rp, D_MODEL / BK, aoff, boff, c, tid);

    // epilogue: bias + relu -> fp16 g_H16 (register-direct)
    int lrow = lane >> 2, lcol2 = (lane & 3) * 2;
#pragma unroll
    for (int nt = 0; nt < 4; nt++) {
        int col = n0 + wc * 32 + nt * 8 + lcol2;
        float bb0 = b1[e * F_DIM + col];
        float bb1 = b1[e * F_DIM + col + 1];
#pragma unroll
        for (int mt = 0; mt < 4; mt++) {
            int r0 = m0 + wr * 64 + mt * 16 + lrow;
#pragma unroll
            for (int h = 0; h < 2; h++) {
                int r = r0 + h * 8;
                if (r < cnt) {
                    float v0 = fmaxf(c[mt][nt][h * 2 + 0] + bb0, 0.f);
                    float v1 = fmaxf(c[mt][nt][h * 2 + 1] + bb1, 0.f);
                    size_t o = ((size_t)e * MAXP + r) * F_DIM + col;
                    *(__half2*)(g_H16 + o) = __floats2half2_rn(v0, v1);
                }
            }
        }
    }
}

// ---------------------------------------------------------------------------
// GEMM2: O[e-rows, D] = wt * ( H @ W2[e] + b2[e] )
__global__ void __launch_bounds__(256, 2)
gemm2_mma(const float* __restrict__ b2) {
    extern __shared__ __align__(16) char tiles[];
    uint32_t smbase = smem_u32(tiles);
    int e   = blockIdx.z;
    int cnt = g_counts[e];
    int m0  = blockIdx.y * BM;
    if (m0 >= cnt) return;
    int n0  = blockIdx.x * BN;
    int tid = threadIdx.x, lane = tid & 31, wid = tid >> 5;
    int wr = wid >> 2, wc = wid & 3;

    int arow = m0 + (tid >> 1); if (arow >= cnt) arow = cnt - 1;
    Ptrs rp;
    rp.a = (const uint4*)(g_H16 + ((size_t)e * MAXP + arow) * F_DIM);
    // B source: native [f][d]
    rp.b = (const uint4*)(g_W2c + ((size_t)e * F_DIM + (tid >> 3)) * D_MODEL
                          + n0 + (tid & 7) * 16);
    rp.bstride = BK * D_MODEL / 8;

    uint32_t aoff[4], boff[2];
    make_offsets(wr, wc, lane, aoff, boff);

    float c[4][4][4];
#pragma unroll
    for (int i = 0; i < 4; i++)
#pragma unroll
        for (int j = 0; j < 4; j++)
#pragma unroll
            for (int k = 0; k < 4; k++) c[i][j][k] = 0.f;

    run_mainloop(smbase, rp, F_DIM / BK, aoff, boff, c, tid);

    // epilogue: (acc + bias) * wt -> g_O (fp32)
    int lrow = lane >> 2, lcol2 = (lane & 3) * 2;
#pragma unroll
    for (int nt = 0; nt < 4; nt++) {
        int col = n0 + wc * 32 + nt * 8 + lcol2;
        float bb0 = b2[e * D_MODEL + col];
        float bb1 = b2[e * D_MODEL + col + 1];
#pragma unroll
        for (int mt = 0; mt < 4; mt++) {
            int r0 = m0 + wr * 64 + mt * 16 + lrow;
#pragma unroll
            for (int h = 0; h < 2; h++) {
                int r = r0 + h * 8;
                if (r < cnt) {
                    float wt = g_wt[e * MAXP + r];
                    float2 o;
                    o.x = (c[mt][nt][h * 2 + 0] + bb0) * wt;
                    o.y = (c[mt][nt][h * 2 + 1] + bb1) * wt;
                    *(float2*)(g_O + ((size_t)e * MAXP + r) * D_MODEL + col) = o;
                }
            }
        }
    }
}

// ---------------------------------------------------------------------------
__global__ void ln_kernel(const float* __restrict__ x,
                          const float* __restrict__ gamma,
                          const float* __restrict__ beta,
                          float* __restrict__ out) {
    int t   = blockIdx.x;
    int tid = threadIdx.x;
    int s0 = g_slot[t * 2 + 0];
    int s1 = g_slot[t * 2 + 1];

    const float4* xr = (const float4*)(x + (size_t)t * D_MODEL);
    const float4* o0 = (const float4*)(g_O + (size_t)s0 * D_MODEL);
    const float4* o1 = (const float4*)(g_O + (size_t)s1 * D_MODEL);

    float4 xv = xr[tid];
    float4 a  = o0[tid];
    float4 b  = o1[tid];
    float4 y;
    y.x = xv.x + a.x + b.x;
    y.y = xv.y + a.y + b.y;
    y.z = xv.z + a.z + b.z;
    y.w = xv.w + a.w + b.w;

    float s  = y.x + y.y + y.z + y.w;
    float sq = y.x * y.x + y.y * y.y + y.z * y.z + y.w * y.w;
#pragma unroll
    for (int off = 16; off > 0; off >>= 1) {
        s  += __shfl_down_sync(0xffffffffu, s,  off);
        sq += __shfl_down_sync(0xffffffffu, sq, off);
    }
    int warp = tid >> 5, lane = tid & 31;
    __shared__ float ws[8], wq[8], red[2];
    if (lane == 0) { ws[warp] = s; wq[warp] = sq; }
    __syncthreads();
    if (tid == 0) {
        float ts = 0.f, tq = 0.f;
#pragma unroll
        for (int i = 0; i < 8; i++) { ts += ws[i]; tq += wq[i]; }
        red[0] = ts; red[1] = tq;
    }
    __syncthreads();

    float mu  = red[0] * (1.0f / D_MODEL);
    float var = red[1] * (1.0f / D_MODEL) - mu * mu;
    float inv = rsqrtf(var + LN_EPS);

    float4 g  = ((const float4*)gamma)[tid];
    float4 bt = ((const float4*)beta)[tid];
    float4 o;
    o.x = g.x * (y.x - mu) * inv + bt.x;
    o.y = g.y * (y.y - mu) * inv + bt.y;
    o.z = g.z * (y.z - mu) * inv + bt.z;
    o.w = g.w * (y.w - mu) * inv + bt.w;
    ((float4*)out)[(size_t)t * (D_MODEL / 4) + tid] = o;
}

// ---------------------------------------------------------------------------
extern "C" void kernel_launch(void* const* d_in, const int* in_sizes, int n_in,
                              void* d_out, int out_size) {
    const float* x     = (const float*)d_in[0];
    const float* Wg    = (const float*)d_in[1];
    const float* bg    = (const float*)d_in[2];
    const float* W1    = (const float*)d_in[3];
    const float* b1    = (const float*)d_in[4];
    const float* W2    = (const float*)d_in[5];
    const float* b2    = (const float*)d_in[6];
    const float* gamma = (const float*)d_in[7];
    const float* beta  = (const float*)d_in[8];
    float* out = (float*)d_out;

    cudaFuncSetAttribute(gemm1_mma, cudaFuncAttributeMaxDynamicSharedMemorySize, SMEM_BYTES);
    cudaFuncSetAttribute(gemm2_mma, cudaFuncAttributeMaxDynamicSharedMemorySize, SMEM_BYTES);

    init_kernel<<<1, 32>>>();
    gating_kernel<<<T_TOKENS / 8, 256>>>(x, Wg, bg);
    conv_w1_kernel<<<(int)((size_t)N_EXP * D_MODEL * F_DIM / 4 / 256), 256>>>(W1);
    conv_w2_kernel<<<(int)((size_t)N_EXP * F_DIM * D_MODEL / 4 / 256), 256>>>(W2);

    gemm1_mma<<<dim3(F_DIM / BN, MAXP / BM, N_EXP), 256, SMEM_BYTES>>>(b1);
    gemm2_mma<<<dim3(D_MODEL / BN, MAXP / BM, N_EXP), 256, SMEM_BYTES>>>(b2);

    ln_kernel<<<T_TOKENS, 256>>>(x, gamma, beta, out);
}

// round 11
// speedup vs baseline: 1.0556x; 1.0556x over previous
#include <cuda_runtime.h>
#include <cuda_fp16.h>
#include <stdint.h>
#include <math.h>

#define T_TOKENS 4096
#define D_MODEL  1024
#define N_EXP    8
#define F_DIM    2048
#define LN_EPS   1e-5f
#define MAXP     4096

// tiles
#define BM 128
#define BN 128
#define BK 32
#define STAGES 4
#define ROWB 80                         // 64B data + 16B pad: 20-word stride, conflict-free
#define BUFB (128 * ROWB)               // 10240 bytes per operand buffer
#define A_OFF 0
#define B_OFF BUFB
#define STG_BYTES (2 * BUFB)            // 20480 per stage
#define SMEM_BYTES (STAGES * STG_BYTES) // 81920 dynamic -> still 2 CTAs/SM

__device__ __forceinline__ void mma16816(float* c, const uint32_t* a, const uint32_t* b) {
    asm volatile(
        "mma.sync.aligned.m16n8k16.row.col.f32.f16.f16.f32 "
        "{%0,%1,%2,%3}, {%4,%5,%6,%7}, {%8,%9}, {%0,%1,%2,%3};"
        : "+f"(c[0]), "+f"(c[1]), "+f"(c[2]), "+f"(c[3])
        : "r"(a[0]), "r"(a[1]), "r"(a[2]), "r"(a[3]), "r"(b[0]), "r"(b[1]));
}
__device__ __forceinline__ uint32_t smem_u32(const void* p) {
    uint32_t a;
    asm("{ .reg .u64 t; cvta.to.shared.u64 t, %1; cvt.u32.u64 %0, t; }"
        : "=r"(a) : "l"(p));
    return a;
}
__device__ __forceinline__ void cp16(uint32_t saddr, const void* g) {
    asm volatile("cp.async.cg.shared.global [%0], [%1], 16;"
                 :: "r"(saddr), "l"(g) : "memory");
}
#define CP_COMMIT() asm volatile("cp.async.commit_group;" ::: "memory")
#define CP_WAIT2()  asm volatile("cp.async.wait_group 2;" ::: "memory")

// ldmatrix.x4: returns the 4 address-group 8x8 matrices in r0..r3.
__device__ __forceinline__ void ldsm4(uint32_t* r, uint32_t addr) {
    asm volatile("ldmatrix.sync.aligned.m8n8.x4.shared.b16 {%0,%1,%2,%3}, [%4];"
                 : "=r"(r[0]), "=r"(r[1]), "=r"(r[2]), "=r"(r[3]) : "r"(addr));
}

// ---------------- scratch ----------------
__device__ int   g_counts[N_EXP];
__device__ int   g_tok[N_EXP * MAXP];
__device__ float g_wt[N_EXP * MAXP];
__device__ int   g_slot[T_TOKENS * 2];
__device__ __align__(16) __half g_x16[(size_t)T_TOKENS * D_MODEL];
__device__ __align__(16) __half g_W1t[(size_t)N_EXP * F_DIM * D_MODEL]; // [e][f][d]
__device__ __align__(16) __half g_W2t[(size_t)N_EXP * D_MODEL * F_DIM]; // [e][d][f]
__device__ __align__(16) __half g_H16[(size_t)N_EXP * MAXP * F_DIM];
__device__ __align__(16) float  g_O[(size_t)N_EXP * MAXP * D_MODEL];

// ---------------------------------------------------------------------------
__global__ void init_kernel() {
    if (threadIdx.x < N_EXP) g_counts[threadIdx.x] = 0;
}

// ---------------------------------------------------------------------------
// Gating + fused fp32->fp16 conversion of x (proven in R10).
__global__ void gating_kernel(const float* __restrict__ x,
                              const float* __restrict__ Wg,
                              const float* __restrict__ bg) {
    int warp = threadIdx.x >> 5;
    int lane = threadIdx.x & 31;
    int t = blockIdx.x * 8 + warp;
    if (t >= T_TOKENS) return;

    float acc[8];
#pragma unroll
    for (int e = 0; e < 8; e++) acc[e] = 0.f;
    const float* xr = x + (size_t)t * D_MODEL;
    __half* xo = g_x16 + (size_t)t * D_MODEL;
    for (int k = lane; k < D_MODEL; k += 32) {
        float xv = xr[k];
        xo[k] = __float2half_rn(xv);
        float4 w0 = *(const float4*)(Wg + (size_t)k * 8);
        float4 w1 = *(const float4*)(Wg + (size_t)k * 8 + 4);
        acc[0] += xv * w0.x; acc[1] += xv * w0.y;
        acc[2] += xv * w0.z; acc[3] += xv * w0.w;
        acc[4] += xv * w1.x; acc[5] += xv * w1.y;
        acc[6] += xv * w1.z; acc[7] += xv * w1.w;
    }
#pragma unroll
    for (int e = 0; e < 8; e++)
#pragma unroll
        for (int off = 16; off > 0; off >>= 1)
            acc[e] += __shfl_down_sync(0xffffffffu, acc[e], off);

    if (lane == 0) {
        float v[8];
#pragma unroll
        for (int e = 0; e < 8; e++) v[e] = acc[e] + bg[e];
        int b0 = 0; float m0 = v[0];
#pragma unroll
        for (int e = 1; e < 8; e++) if (v[e] > m0) { m0 = v[e]; b0 = e; }
        int b1i = (b0 == 0) ? 1 : 0; float m1 = v[b1i];
#pragma unroll
        for (int e = 0; e < 8; e++)
            if (e != b0 && v[e] > m1) { m1 = v[e]; b1i = e; }

        float ex = expf(m1 - m0);
        float s  = 1.0f + ex;
        int p0 = atomicAdd(&g_counts[b0], 1);
        g_tok[b0 * MAXP + p0] = t;
        g_wt [b0 * MAXP + p0] = 1.0f / s;
        g_slot[t * 2 + 0] = b0 * MAXP + p0;
        int p1 = atomicAdd(&g_counts[b1i], 1);
        g_tok[b1i * MAXP + p1] = t;
        g_wt [b1i * MAXP + p1] = ex / s;
        g_slot[t * 2 + 1] = b1i * MAXP + p1;
    }
}

// ---------------------------------------------------------------------------
// W [E][R][C] fp32 -> fp16 [E][C][R], half2 (4B) stores for coalescing.
// Output pointer MUST be a device-resolved symbol (GB300 ATS: host-shadow
// addresses silently write host memory — the R3-R5 zero-weights bug).
__device__ __forceinline__ void transpose_body(const float* __restrict__ W,
                                               __half* __restrict__ dst,
                                               int R, int C) {
    __shared__ float t[64][33];
    int e  = blockIdx.z;
    int c0 = blockIdx.x * 32, r0 = blockIdx.y * 64;
    int tx = threadIdx.x, ty = threadIdx.y;
    const float* Wp = W + (size_t)e * R * C;
#pragma unroll
    for (int i = 0; i < 8; i++)
        t[ty + i * 8][tx] = Wp[(size_t)(r0 + ty + i * 8) * C + (c0 + tx)];
    __syncthreads();
    size_t ob = (size_t)e * C * R;
#pragma unroll
    for (int i = 0; i < 4; i++) {
        int c = ty + i * 8;   // 0..31
        __half2 v = __floats2half2_rn(t[tx * 2][c], t[tx * 2 + 1][c]);
        *(__half2*)(dst + ob + (size_t)(c0 + c) * R + r0 + tx * 2) = v;
    }
}
__global__ void transpose_w1_kernel(const float* __restrict__ W) {
    transpose_body(W, g_W1t, D_MODEL, F_DIM);
}
__global__ void transpose_w2_kernel(const float* __restrict__ W) {
    transpose_body(W, g_W2t, F_DIM, D_MODEL);
}

// ---------------------------------------------------------------------------
// HMMA mainloop, cp.async 4-stage pipelined, fp16 single-pass, ldmatrix loads.
// smem writer contract: element (row, k_local) of each operand buffer lives at
//   stage_base + buf_off + row*ROWB + 2*k_local
struct RowPtrs {
    const uint4* a;
    const uint4* b;
};

__device__ __forceinline__ void cp_stage(uint32_t smbase, const RowPtrs& rp,
                                         int s, int kt, int row, int half) {
    uint32_t off = (uint32_t)row * ROWB + (uint32_t)half * 32u;
    uint32_t b   = smbase + s * STG_BYTES + off;
    int idx = kt * 4 + half * 2;
    cp16(b + A_OFF,      rp.a + idx);
    cp16(b + A_OFF + 16, rp.a + idx + 1);
    cp16(b + B_OFF,      rp.b + idx);
    cp16(b + B_OFF + 16, rp.b + idx + 1);
}

// ldmatrix address groups (hardware-verified R9):
//   A: g0 rows m..m+7 @k | g1 m+8..15 @k | g2 m..m+7 @k+8 | g3 m+8..15 @k+8
//   B: g0 n..n+7 @k | g1 n..n+7 @k+8 | g2 n+8..15 @k | g3 n+8..15 @k+8
__device__ __forceinline__ void compute_tiles(uint32_t sbase,
                                              const uint32_t aoff[4],
                                              const uint32_t boff[2],
                                              float c[4][4][4]) {
#pragma unroll
    for (int kk = 0; kk < 2; kk++) {
        uint32_t ko = (uint32_t)kk * 32u;
        uint32_t a[4][4], b[2][4];
#pragma unroll
        for (int mt = 0; mt < 4; mt++)
            ldsm4(a[mt], sbase + A_OFF + aoff[mt] + ko);
#pragma unroll
        for (int p = 0; p < 2; p++)
            ldsm4(b[p], sbase + B_OFF + boff[p] + ko);
#pragma unroll
        for (int mt = 0; mt < 4; mt++)
#pragma unroll
            for (int nt = 0; nt < 4; nt++)
                mma16816(c[mt][nt], a[mt], &b[nt >> 1][(nt & 1) * 2]);
    }
}

// One barrier per k-tile. Safety of prefetch(kt+3) into stage (kt-1)%4:
// issued only after sync(kt), which all threads pass only after compute(kt-1).
__device__ __forceinline__ void run_mainloop(uint32_t smbase,
                                             const RowPtrs& rp, int ktiles,
                                             const uint32_t aoff[4],
                                             const uint32_t boff[2],
                                             float c[4][4][4], int row, int half) {
#pragma unroll
    for (int s = 0; s < STAGES - 1; s++) {
        cp_stage(smbase, rp, s, s, row, half);
        CP_COMMIT();
    }
    for (int kt = 0; kt < ktiles; kt++) {
        CP_WAIT2();
        __syncthreads();
        int kn = kt + STAGES - 1;
        if (kn < ktiles) cp_stage(smbase, rp, kn % STAGES, kn, row, half);
        CP_COMMIT();
        compute_tiles(smbase + (kt % STAGES) * STG_BYTES, aoff, boff, c);
    }
}

// lane offsets for ldmatrix (relative to operand buffer base)
__device__ __forceinline__ void make_offsets(int wr, int wc, int lane,
                                             uint32_t aoff[4], uint32_t boff[2]) {
#pragma unroll
    for (int mt = 0; mt < 4; mt++)
        aoff[mt] = (uint32_t)(wr * 64 + mt * 16 + (lane & 15)) * ROWB
                 + (uint32_t)(lane >> 4) * 16u;
#pragma unroll
    for (int p = 0; p < 2; p++)
        boff[p] = (uint32_t)(wc * 32 + p * 16 + ((lane >> 4) << 3) + (lane & 7)) * ROWB
                + (uint32_t)((lane >> 3) & 1) * 16u;
}

// ---------------------------------------------------------------------------
// GEMM1: H[e-rows, F] = relu( Xg @ W1t[e] + b1[e] ), fp16 single-pass
__global__ void __launch_bounds__(256, 2)
gemm1_mma(const float* __restrict__ b1) {
    extern __shared__ __align__(16) char tiles[];
    uint32_t smbase = smem_u32(tiles);
    int e   = blockIdx.z;
    int cnt = g_counts[e];
    int m0  = blockIdx.y * BM;
    if (m0 >= cnt) return;
    int n0  = blockIdx.x * BN;
    int tid = threadIdx.x, lane = tid & 31, wid = tid >> 5;
    int wr = wid >> 2, wc = wid & 3;
    int row = tid >> 1, half = tid & 1;

    int arow = m0 + row; if (arow >= cnt) arow = cnt - 1;
    int tok  = g_tok[e * MAXP + arow];
    int brow = n0 + row;
    RowPtrs rp;
    rp.a = (const uint4*)(g_x16 + (size_t)tok * D_MODEL);
    rp.b = (const uint4*)(g_W1t + ((size_t)e * F_DIM + brow) * D_MODEL);

    uint32_t aoff[4], boff[2];
    make_offsets(wr, wc, lane, aoff, boff);

    float c[4][4][4];
#pragma unroll
    for (int i = 0; i < 4; i++)
#pragma unroll
        for (int j = 0; j < 4; j++)
#pragma unroll
            for (int k = 0; k < 4; k++) c[i][j][k] = 0.f;

    run_mainloop(smbase, rp, D_MODEL / BK, aoff, boff, c, row, half);

    // epilogue: bias + relu -> fp16 g_H16 (register-direct)
    int lrow = lane >> 2, lcol2 = (lane & 3) * 2;
#pragma unroll
    for (int nt = 0; nt < 4; nt++) {
        int col = n0 + wc * 32 + nt * 8 + lcol2;
        float bb0 = b1[e * F_DIM + col];
        float bb1 = b1[e * F_DIM + col + 1];
#pragma unroll
        for (int mt = 0; mt < 4; mt++) {
            int r0 = m0 + wr * 64 + mt * 16 + lrow;
#pragma unroll
            for (int h = 0; h < 2; h++) {
                int r = r0 + h * 8;
                if (r < cnt) {
                    float v0 = fmaxf(c[mt][nt][h * 2 + 0] + bb0, 0.f);
                    float v1 = fmaxf(c[mt][nt][h * 2 + 1] + bb1, 0.f);
                    size_t o = ((size_t)e * MAXP + r) * F_DIM + col;
                    *(__half2*)(g_H16 + o) = __floats2half2_rn(v0, v1);
                }
            }
        }
    }
}

// ---------------------------------------------------------------------------
// GEMM2: O[e-rows, D] = wt * ( H @ W2t[e] + b2[e] )
__global__ void __launch_bounds__(256, 2)
gemm2_mma(const float* __restrict__ b2) {
    extern __shared__ __align__(16) char tiles[];
    uint32_t smbase = smem_u32(tiles);
    int e   = blockIdx.z;
    int cnt = g_counts[e];
    int m0  = blockIdx.y * BM;
    if (m0 >= cnt) return;
    int n0  = blockIdx.x * BN;
    int tid = threadIdx.x, lane = tid & 31, wid = tid >> 5;
    int wr = wid >> 2, wc = wid & 3;
    int row = tid >> 1, half = tid & 1;

    int arow = m0 + row; if (arow >= cnt) arow = cnt - 1;
    int brow = n0 + row;
    RowPtrs rp;
    rp.a = (const uint4*)(g_H16 + ((size_t)e * MAXP + arow) * F_DIM);
    rp.b = (const uint4*)(g_W2t + ((size_t)e * D_MODEL + brow) * F_DIM);

    uint32_t aoff[4], boff[2];
    make_offsets(wr, wc, lane, aoff, boff);

    float c[4][4][4];
#pragma unroll
    for (int i = 0; i < 4; i++)
#pragma unroll
        for (int j = 0; j < 4; j++)
#pragma unroll
            for (int k = 0; k < 4; k++) c[i][j][k] = 0.f;

    run_mainloop(smbase, rp, F_DIM / BK, aoff, boff, c, row, half);

    // epilogue: (acc + bias) * wt -> g_O (fp32)
    int lrow = lane >> 2, lcol2 = (lane & 3) * 2;
#pragma unroll
    for (int nt = 0; nt < 4; nt++) {
        int col = n0 + wc * 32 + nt * 8 + lcol2;
        float bb0 = b2[e * D_MODEL + col];
        float bb1 = b2[e * D_MODEL + col + 1];
#pragma unroll
        for (int mt = 0; mt < 4; mt++) {
            int r0 = m0 + wr * 64 + mt * 16 + lrow;
#pragma unroll
            for (int h = 0; h < 2; h++) {
                int r = r0 + h * 8;
                if (r < cnt) {
                    float wt = g_wt[e * MAXP + r];
                    float2 o;
                    o.x = (c[mt][nt][h * 2 + 0] + bb0) * wt;
                    o.y = (c[mt][nt][h * 2 + 1] + bb1) * wt;
                    *(float2*)(g_O + ((size_t)e * MAXP + r) * D_MODEL + col) = o;
                }
            }
        }
    }
}

// ---------------------------------------------------------------------------
__global__ void ln_kernel(const float* __restrict__ x,
                          const float* __restrict__ gamma,
                          const float* __restrict__ beta,
                          float* __restrict__ out) {
    int t   = blockIdx.x;
    int tid = threadIdx.x;
    int s0 = g_slot[t * 2 + 0];
    int s1 = g_slot[t * 2 + 1];

    const float4* xr = (const float4*)(x + (size_t)t * D_MODEL);
    const float4* o0 = (const float4*)(g_O + (size_t)s0 * D_MODEL);
    const float4* o1 = (const float4*)(g_O + (size_t)s1 * D_MODEL);

    float4 xv = xr[tid];
    float4 a  = o0[tid];
    float4 b  = o1[tid];
    float4 y;
    y.x = xv.x + a.x + b.x;
    y.y = xv.y + a.y + b.y;
    y.z = xv.z + a.z + b.z;
    y.w = xv.w + a.w + b.w;

    float s  = y.x + y.y + y.z + y.w;
    float sq = y.x * y.x + y.y * y.y + y.z * y.z + y.w * y.w;
#pragma unroll
    for (int off = 16; off > 0; off >>= 1) {
        s  += __shfl_down_sync(0xffffffffu, s,  off);
        sq += __shfl_down_sync(0xffffffffu, sq, off);
    }
    int warp = tid >> 5, lane = tid & 31;
    __shared__ float ws[8], wq[8], red[2];
    if (lane == 0) { ws[warp] = s; wq[warp] = sq; }
    __syncthreads();
    if (tid == 0) {
        float ts = 0.f, tq = 0.f;
#pragma unroll
        for (int i = 0; i < 8; i++) { ts += ws[i]; tq += wq[i]; }
        red[0] = ts; red[1] = tq;
    }
    __syncthreads();

    float mu  = red[0] * (1.0f / D_MODEL);
    float var = red[1] * (1.0f / D_MODEL) - mu * mu;
    float inv = rsqrtf(var + LN_EPS);

    float4 g  = ((const float4*)gamma)[tid];
    float4 bt = ((const float4*)beta)[tid];
    float4 o;
    o.x = g.x * (y.x - mu) * inv + bt.x;
    o.y = g.y * (y.y - mu) * inv + bt.y;
    o.z = g.z * (y.z - mu) * inv + bt.z;
    o.w = g.w * (y.w - mu) * inv + bt.w;
    ((float4*)out)[(size_t)t * (D_MODEL / 4) + tid] = o;
}

// ---------------------------------------------------------------------------
extern "C" void kernel_launch(void* const* d_in, const int* in_sizes, int n_in,
                              void* d_out, int out_size) {
    const float* x     = (const float*)d_in[0];
    const float* Wg    = (const float*)d_in[1];
    const float* bg    = (const float*)d_in[2];
    const float* W1    = (const float*)d_in[3];
    const float* b1    = (const float*)d_in[4];
    const float* W2    = (const float*)d_in[5];
    const float* b2    = (const float*)d_in[6];
    const float* gamma = (const float*)d_in[7];
    const float* beta  = (const float*)d_in[8];
    float* out = (float*)d_out;

    cudaFuncSetAttribute(gemm1_mma, cudaFuncAttributeMaxDynamicSharedMemorySize, SMEM_BYTES);
    cudaFuncSetAttribute(gemm2_mma, cudaFuncAttributeMaxDynamicSharedMemorySize, SMEM_BYTES);

    init_kernel<<<1, 32>>>();
    gating_kernel<<<T_TOKENS / 8, 256>>>(x, Wg, bg);
    transpose_w1_kernel<<<dim3(F_DIM / 32, D_MODEL / 64, N_EXP), dim3(32, 8)>>>(W1);
    transpose_w2_kernel<<<dim3(D_MODEL / 32, F_DIM / 64, N_EXP), dim3(32, 8)>>>(W2);

    gemm1_mma<<<dim3(F_DIM / BN, MAXP / BM, N_EXP), 256, SMEM_BYTES>>>(b1);
    gemm2_mma<<<dim3(D_MODEL / BN, MAXP / BM, N_EXP), 256, SMEM_BYTES>>>(b2);

    ln_kernel<<<T_TOKENS, 256>>>(x, gamma, beta, out);
}